// round 4
// baseline (speedup 1.0000x reference)
#include <cuda_runtime.h>
#include <cstdint>

#define N_NODES 8192
#define F_DIM 128
#define ALPHA 0.3f
#define MAXDEG 512

__device__ __forceinline__ uint32_t f2tf32(float x) {
    uint32_t r;
    asm("cvt.rna.tf32.f32 %0, %1;" : "=r"(r) : "f"(x));
    return r;
}

// ---- device scratch (no allocations allowed) ----
__device__ float    g_v[4 * F_DIM];
__device__ float    g_Sx[F_DIM];
__device__ float    g_sa1[2 * N_NODES];
__device__ float    g_sa2[2 * N_NODES];
__device__ uint32_t g_Ghi[(size_t)N_NODES * 256];   // tf32 hi bits of G
__device__ uint32_t g_Glo[(size_t)N_NODES * 256];   // tf32 lo bits of G
__device__ uint32_t g_Khi[256 * 128];
__device__ uint32_t g_Klo[256 * 128];

// ============================================================
// Kernel 1: v vectors; zero Sx
// ============================================================
__global__ void prep_kernel(const float* __restrict__ Wmap,
                            const float* __restrict__ a1w,
                            const float* __restrict__ a2w) {
    int t = threadIdx.x;          // 256 -> (h,f)
    int h = t >> 7, f = t & 127;
    const float* wrow = Wmap + (size_t)(h * F_DIM + f) * 128;
    float s1 = 0.f, s2 = 0.f;
    for (int d = 0; d < 128; ++d) {
        float w = wrow[d];
        s1 = fmaf(w, a1w[h * 128 + d], s1);
        s2 = fmaf(w, a2w[h * 128 + d], s2);
    }
    g_v[h * F_DIM + f] = s1;
    g_v[2 * F_DIM + h * F_DIM + f] = s2;
    if (t < F_DIM) g_Sx[t] = 0.f;
}

// Kernel 1b: presplit Kw into tf32 hi/lo   (grid 128 x 256)
__global__ void prep2_kernel(const float* __restrict__ Kw) {
    int idx = blockIdx.x * 256 + threadIdx.x;
    float v = Kw[idx];
    uint32_t hi = f2tf32(v);
    g_Khi[idx] = hi;
    g_Klo[idx] = f2tf32(v - __uint_as_float(hi));
}

// ============================================================
// Kernel 2: per-node scores sa1/sa2 + fused column sums of x
// ============================================================
__global__ void __launch_bounds__(256) score_kernel(const float* __restrict__ x,
                                                    const float* __restrict__ a1b,
                                                    const float* __restrict__ a2b) {
    __shared__ float sv[4 * 128];
    __shared__ float s_colp[8][128];
    int tid = threadIdx.x;
    sv[tid] = g_v[tid];
    sv[256 + tid] = g_v[256 + tid];

    int warp = tid >> 5, lane = tid & 31;
    int n = blockIdx.x * 8 + warp;
    const float* xr = x + (size_t)n * F_DIM;
    float x0 = xr[lane], x1 = xr[lane + 32], x2 = xr[lane + 64], x3 = xr[lane + 96];

    s_colp[warp][lane]      = x0;
    s_colp[warp][lane + 32] = x1;
    s_colp[warp][lane + 64] = x2;
    s_colp[warp][lane + 96] = x3;
    __syncthreads();

    float s[4];
    #pragma unroll
    for (int q = 0; q < 4; ++q) {
        const float* v = sv + q * 128;
        float acc = x0 * v[lane] + x1 * v[lane + 32] + x2 * v[lane + 64] + x3 * v[lane + 96];
        #pragma unroll
        for (int o = 16; o > 0; o >>= 1)
            acc += __shfl_down_sync(0xffffffffu, acc, o);
        s[q] = acc;
    }
    if (lane == 0) {
        g_sa1[n]           = s[0] + a1b[0];
        g_sa1[N_NODES + n] = s[1] + a1b[1];
        g_sa2[n]           = s[2] + a2b[0];
        g_sa2[N_NODES + n] = s[3] + a2b[1];
    }
    if (tid < 128) {
        float cs = 0.f;
        #pragma unroll
        for (int w = 0; w < 8; ++w) cs += s_colp[w][tid];
        atomicAdd(&g_Sx[tid], cs);
    }
}

// ============================================================
// Kernel 3 (main): adj scan -> no-max sparse softmax -> gather
// ============================================================
__global__ void __launch_bounds__(256) gat_main(const float* __restrict__ adj,
                                                const float* __restrict__ x) {
    __shared__ int   s_list[MAXDEG];
    __shared__ float s_w0[MAXDEG], s_w1[MAXDEG];
    __shared__ float s_p0[8][132], s_p1[8][132];
    __shared__ int   s_cnt;
    __shared__ float s_red[16];
    __shared__ float s_bc[2];

    int tid = threadIdx.x;
    int i = blockIdx.x;
    if (tid == 0) s_cnt = 0;
    __syncthreads();

    // ---- phase 1: streaming scan, 2 batches of 4 (MLP=4) ----
    const uint4* arow = reinterpret_cast<const uint4*>(adj + (size_t)i * N_NODES);
    #pragma unroll
    for (int half = 0; half < 2; ++half) {
        uint4 a[4];
        #pragma unroll
        for (int it = 0; it < 4; ++it)
            a[it] = __ldcs(&arow[(half * 4 + it) * 256 + tid]);
        #pragma unroll
        for (int it = 0; it < 4; ++it) {
            uint4 v = a[it];
            if ((v.x | v.y | v.z | v.w) != 0u) {
                int jb = ((half * 4 + it) * 256 + tid) << 2;
                if (v.x) { int p = atomicAdd(&s_cnt, 1); if (p < MAXDEG) s_list[p] = jb; }
                if (v.y) { int p = atomicAdd(&s_cnt, 1); if (p < MAXDEG) s_list[p] = jb + 1; }
                if (v.z) { int p = atomicAdd(&s_cnt, 1); if (p < MAXDEG) s_list[p] = jb + 2; }
                if (v.w) { int p = atomicAdd(&s_cnt, 1); if (p < MAXDEG) s_list[p] = jb + 3; }
            }
        }
    }
    __syncthreads();
    int deg = min(s_cnt, MAXDEG);

    float sa1_0 = g_sa1[i];
    float sa1_1 = g_sa1[N_NODES + i];

    // ---- phase 2: leaky + exp + sum (NO max-sub: scores are O(10), safe) ----
    float z0 = 0.f, z1 = 0.f;
    for (int t = tid; t < deg; t += 256) {
        int j = s_list[t];
        float w0 = sa1_0 + g_sa2[j];
        float w1 = sa1_1 + g_sa2[N_NODES + j];
        w0 = (w0 >= 0.f) ? w0 : ALPHA * w0;
        w1 = (w1 >= 0.f) ? w1 : ALPHA * w1;
        float e0 = __expf(w0);
        float e1 = __expf(w1);
        s_w0[t] = e0; s_w1[t] = e1;
        z0 += e0; z1 += e1;
    }
    #pragma unroll
    for (int o = 16; o > 0; o >>= 1) {
        z0 += __shfl_down_sync(0xffffffffu, z0, o);
        z1 += __shfl_down_sync(0xffffffffu, z1, o);
    }
    if ((tid & 31) == 0) { s_red[tid >> 5] = z0; s_red[8 + (tid >> 5)] = z1; }
    __syncthreads();
    if (tid == 0) {
        float p = 0.f, q = 0.f;
        #pragma unroll
        for (int w = 0; w < 8; ++w) { p += s_red[w]; q += s_red[8 + w]; }
        s_bc[0] = p + (float)(N_NODES - deg);   // non-neighbors contribute exp(0)=1
        s_bc[1] = q + (float)(N_NODES - deg);
    }
    __syncthreads();
    float iz0 = 1.f / s_bc[0];
    float iz1 = 1.f / s_bc[1];

    // ---- phase 3: gather (8 slots x 32 lanes, float4); beta=(e-1)*iz folded ----
    int lane = tid & 31;
    int slot = tid >> 5;
    const float4* x4 = reinterpret_cast<const float4*>(x);
    float g0a = 0.f, g0b = 0.f, g0c = 0.f, g0d = 0.f;
    float g1a = 0.f, g1b = 0.f, g1c = 0.f, g1d = 0.f;
    #pragma unroll 2
    for (int t = slot; t < deg; t += 8) {
        int j = s_list[t];
        float4 xv = __ldg(&x4[(size_t)j * 32 + lane]);
        float b0 = (s_w0[t] - 1.f) * iz0;
        float b1 = (s_w1[t] - 1.f) * iz1;
        g0a = fmaf(b0, xv.x, g0a); g1a = fmaf(b1, xv.x, g1a);
        g0b = fmaf(b0, xv.y, g0b); g1b = fmaf(b1, xv.y, g1b);
        g0c = fmaf(b0, xv.z, g0c); g1c = fmaf(b1, xv.z, g1c);
        g0d = fmaf(b0, xv.w, g0d); g1d = fmaf(b1, xv.w, g1d);
    }
    *reinterpret_cast<float4*>(&s_p0[slot][lane * 4]) = make_float4(g0a, g0b, g0c, g0d);
    *reinterpret_cast<float4*>(&s_p1[slot][lane * 4]) = make_float4(g1a, g1b, g1c, g1d);
    __syncthreads();

    if (tid < 128) {
        float v0 = 0.f, v1 = 0.f;
        #pragma unroll
        for (int s = 0; s < 8; ++s) { v0 += s_p0[s][tid]; v1 += s_p1[s][tid]; }
        float sx = g_Sx[tid];
        v0 = fmaf(iz0, sx, v0);                 // rank-1 term coeff = 1/Z
        v1 = fmaf(iz1, sx, v1);
        size_t o = (size_t)i * 256 + tid;
        uint32_t h0 = f2tf32(v0);
        g_Ghi[o] = h0;
        g_Glo[o] = f2tf32(v0 - __uint_as_float(h0));
        uint32_t h1 = f2tf32(v1);
        g_Ghi[o + 128] = h1;
        g_Glo[o + 128] = f2tf32(v1 - __uint_as_float(h1));
    }
}

// ============================================================
// Kernel 4: out = 0.5*(G @ Kflat + bias0 + bias1) via tf32 MMA.
// Presplit operands, BM=32, BN=128, BK=16, 256 thr, grid 256, dbl-buffered.
// ============================================================
__device__ __forceinline__ void mma_tf32(float* d, const uint32_t* a, const uint32_t* b) {
    asm volatile(
        "mma.sync.aligned.m16n8k8.row.col.f32.tf32.tf32.f32 "
        "{%0,%1,%2,%3},{%4,%5,%6,%7},{%8,%9},{%0,%1,%2,%3};\n"
        : "+f"(d[0]), "+f"(d[1]), "+f"(d[2]), "+f"(d[3])
        : "r"(a[0]), "r"(a[1]), "r"(a[2]), "r"(a[3]), "r"(b[0]), "r"(b[1]));
}

__global__ void __launch_bounds__(256) gemm_tf32(const float* __restrict__ bias,
                                                 float* __restrict__ out) {
    __shared__ uint32_t Ah[2][16][40], Al[2][16][40];    // [buf][k][m]
    __shared__ uint32_t Bh[2][16][136], Bl[2][16][136];  // [buf][k][col]

    int tid = threadIdx.x;
    int wid = tid >> 5, lane = tid & 31;
    int grp = lane >> 2, thr = lane & 3;
    int wm = wid & 1;            // 2 m-groups of 16 rows
    int wn = wid >> 1;           // 4 n-groups of 32 cols
    int row0 = blockIdx.x * 32;
    int cb = wn * 32;
    int m0 = wm * 16;

    // staging indices
    int am  = tid >> 3;          // 0..31 rows
    int ak2 = (tid & 7) * 2;     // k pair
    int bkr = tid >> 5;          // 0..7 k rows (and +8)
    int bc4 = (tid & 31) * 4;    // col quad

    uint2 rah, ral;
    uint4 rbh[2], rbl[2];

    auto ldg_chunk = [&](int c) {
        int kb = c * 16;
        size_t ao = (size_t)(row0 + am) * 256 + kb + ak2;
        rah = *reinterpret_cast<const uint2*>(&g_Ghi[ao]);
        ral = *reinterpret_cast<const uint2*>(&g_Glo[ao]);
        #pragma unroll
        for (int q = 0; q < 2; ++q) {
            size_t bo = (size_t)(kb + bkr + 8 * q) * 128 + bc4;
            rbh[q] = *reinterpret_cast<const uint4*>(&g_Khi[bo]);
            rbl[q] = *reinterpret_cast<const uint4*>(&g_Klo[bo]);
        }
    };
    auto sts_chunk = [&](int buf) {
        Ah[buf][ak2][am] = rah.x; Ah[buf][ak2 + 1][am] = rah.y;
        Al[buf][ak2][am] = ral.x; Al[buf][ak2 + 1][am] = ral.y;
        #pragma unroll
        for (int q = 0; q < 2; ++q) {
            *reinterpret_cast<uint4*>(&Bh[buf][bkr + 8 * q][bc4]) = rbh[q];
            *reinterpret_cast<uint4*>(&Bl[buf][bkr + 8 * q][bc4]) = rbl[q];
        }
    };

    float acc[4][4];
    #pragma unroll
    for (int ni = 0; ni < 4; ++ni)
        #pragma unroll
        for (int q = 0; q < 4; ++q) acc[ni][q] = 0.f;

    ldg_chunk(0);
    sts_chunk(0);
    __syncthreads();

    #pragma unroll 1
    for (int c = 0; c < 16; ++c) {
        int cur = c & 1;
        if (c < 15) ldg_chunk(c + 1);

        #pragma unroll
        for (int k8 = 0; k8 < 2; ++k8) {
            int kb = k8 * 8;
            uint32_t ah[4], al[4];
            ah[0] = Ah[cur][kb + thr][m0 + grp];
            ah[1] = Ah[cur][kb + thr][m0 + grp + 8];
            ah[2] = Ah[cur][kb + thr + 4][m0 + grp];
            ah[3] = Ah[cur][kb + thr + 4][m0 + grp + 8];
            al[0] = Al[cur][kb + thr][m0 + grp];
            al[1] = Al[cur][kb + thr][m0 + grp + 8];
            al[2] = Al[cur][kb + thr + 4][m0 + grp];
            al[3] = Al[cur][kb + thr + 4][m0 + grp + 8];
            #pragma unroll
            for (int ni = 0; ni < 4; ++ni) {
                uint32_t bh[2], bl[2];
                int cc = cb + ni * 8 + grp;
                bh[0] = Bh[cur][kb + thr][cc];
                bh[1] = Bh[cur][kb + thr + 4][cc];
                bl[0] = Bl[cur][kb + thr][cc];
                bl[1] = Bl[cur][kb + thr + 4][cc];
                mma_tf32(acc[ni], ah, bh);
                mma_tf32(acc[ni], ah, bl);
                mma_tf32(acc[ni], al, bh);
            }
        }

        if (c < 15) {
            sts_chunk(cur ^ 1);
            __syncthreads();
        }
    }

    // epilogue
    #pragma unroll
    for (int ni = 0; ni < 4; ++ni) {
        int c0 = cb + ni * 8 + 2 * thr;
        #pragma unroll
        for (int half = 0; half < 2; ++half) {
            int r = row0 + m0 + grp + half * 8;
            size_t o = (size_t)r * 128 + c0;
            const float2 b0 = *reinterpret_cast<const float2*>(bias + o);
            const float2 b1 = *reinterpret_cast<const float2*>(bias + (size_t)N_NODES * 128 + o);
            float2 res;
            res.x = 0.5f * (acc[ni][half * 2 + 0] + b0.x + b1.x);
            res.y = 0.5f * (acc[ni][half * 2 + 1] + b0.y + b1.y);
            *reinterpret_cast<float2*>(out + o) = res;
        }
    }
}

// ============================================================
extern "C" void kernel_launch(void* const* d_in, const int* in_sizes, int n_in,
                              void* d_out, int out_size) {
    const float* x    = (const float*)d_in[0];
    const float* adj  = (const float*)d_in[1];
    const float* Wmap = (const float*)d_in[2];
    const float* a1w  = (const float*)d_in[3];
    const float* a1b  = (const float*)d_in[4];
    const float* a2w  = (const float*)d_in[5];
    const float* a2b  = (const float*)d_in[6];
    const float* kern = (const float*)d_in[7];
    const float* bias = (const float*)d_in[8];
    float* out = (float*)d_out;

    prep_kernel<<<1, 256>>>(Wmap, a1w, a2w);
    prep2_kernel<<<128, 256>>>(kern);
    score_kernel<<<1024, 256>>>(x, a1b, a2b);
    gat_main<<<N_NODES, 256>>>(adj, x);
    gemm_tf32<<<256, 256>>>(bias, out);
}